// round 16
// baseline (speedup 1.0000x reference)
#include <cuda_runtime.h>
#include <cuda_fp16.h>
#include <math.h>
#include <stdint.h>

#define Bb   4
#define Ss   512
#define Dd   512
#define Hh   2048
#define Ee   8
#define NTOK (Bb*Ss)
#define NPAIR (NTOK*2)
#define NRB  (NTOK/8)                   // router blocks = 256

#define PLW     68                      // smem row pitch in words (64 used + 4 pad)
#define PLANE_W (128*PLW)               // 8704 words
#define PLANE_B (PLANE_W*4)             // 34816 B
#define STAGE_B (2*PLANE_B)             // Aq, Bq = 69632 B
#define NSTAGE  2
#define TC_SMEM (NSTAGE*STAGE_B)        // 139264 B (1 CTA/SM)

// ---------------- device scratch ----------------
__device__ float    g_base[NTOK*Dd];
__device__ float    g_lnc[NTOK*Dd];     // LN(context) fp32 (router only)
__device__ uint32_t g_xq[NTOK*(Dd/2)];  // x fp16 quantized
__device__ uint32_t g_w1q[Ee*Hh*(Dd/2)];  // W1^T fp16 quantized
__device__ uint32_t g_w2q[Ee*Dd*(Hh/2)];  // W2^T fp16 quantized
__device__ uint32_t g_hq[NPAIR*(Hh/2)];   // h fp16 quantized
__device__ float    g_M[Ee*Dd];         // (ctxW @ rtrW)^T : [e][d]
__device__ float    g_WT[Ee*Dd];        // rtrW^T : [e][d]
__device__ int      g_elist[Ee*NTOK];
__device__ int      g_ecount[Ee];
__device__ float    g_gate[NPAIR];
__device__ float    g_part[NRB*10];     // per-router-block partials

// ---------------- helpers ----------------
__device__ __forceinline__ uint32_t smem_u32_of(const void* p) {
    uint32_t a;
    asm("{ .reg .u64 t; cvta.to.shared.u64 t, %1; cvt.u32.u64 %0, t; }" : "=r"(a) : "l"(p));
    return a;
}
__device__ __forceinline__ uint32_t quant_f16(float x0, float x1) {
    __half2 h = __floats2half2_rn(x0, x1);
    return *reinterpret_cast<uint32_t*>(&h);
}
__device__ __forceinline__ void mma_f16(float c[4],
        uint32_t a0, uint32_t a1, uint32_t a2, uint32_t a3, uint32_t b0, uint32_t b1) {
    asm volatile(
        "mma.sync.aligned.m16n8k16.row.col.f32.f16.f16.f32 "
        "{%0,%1,%2,%3}, {%4,%5,%6,%7}, {%8,%9}, {%0,%1,%2,%3};"
        : "+f"(c[0]), "+f"(c[1]), "+f"(c[2]), "+f"(c[3])
        : "r"(a0), "r"(a1), "r"(a2), "r"(a3), "r"(b0), "r"(b1));
}
__device__ __forceinline__ void ldsm4(uint32_t a, uint32_t& r0, uint32_t& r1,
                                      uint32_t& r2, uint32_t& r3) {
    asm volatile("ldmatrix.sync.aligned.m8n8.x4.shared.b16 {%0,%1,%2,%3}, [%4];"
        : "=r"(r0), "=r"(r1), "=r"(r2), "=r"(r3) : "r"(a));
}
#define CPA(dst, src) asm volatile("cp.async.cg.shared.global [%0], [%1], 16;" :: "r"(dst), "l"(src))
#define CPA_COMMIT()  asm volatile("cp.async.commit_group;" ::: "memory")
#define CPA_WAIT1()   asm volatile("cp.async.wait_group 1;" ::: "memory")

// ---------------- prep kernels ----------------
__global__ void k_zero_out(float* __restrict__ out) {
    ((float4*)out)[(size_t)blockIdx.x * 256 + threadIdx.x] = make_float4(0.f, 0.f, 0.f, 0.f);
}

// M^T[e][i] = sum_j ctxW[i][j] * rtrW[j][e]; also rtrW^T
__global__ void k_prep_M(const float* __restrict__ ctxW, const float* __restrict__ rtrW) {
    int warp = threadIdx.x >> 5, lane = threadIdx.x & 31;
    int i = blockIdx.x * 8 + warp;
    float acc[8] = {};
#pragma unroll
    for (int jj = 0; jj < 16; jj++) {
        int j = jj*32 + lane;
        float v = ctxW[(size_t)i * Dd + j];
        const float4* w = (const float4*)(rtrW + (size_t)j * Ee);
        float4 w0 = w[0], w1 = w[1];
        acc[0] += v*w0.x; acc[1] += v*w0.y; acc[2] += v*w0.z; acc[3] += v*w0.w;
        acc[4] += v*w1.x; acc[5] += v*w1.y; acc[6] += v*w1.z; acc[7] += v*w1.w;
    }
#pragma unroll
    for (int o = 16; o > 0; o >>= 1)
#pragma unroll
        for (int e = 0; e < 8; e++)
            acc[e] += __shfl_xor_sync(~0u, acc[e], o);
    if (lane < 8) g_M[lane*Dd + i] = acc[lane];
    int gt = blockIdx.x * 256 + threadIdx.x;
    if (gt < Dd*Ee) {
        int j = gt >> 3, e = gt & 7;
        g_WT[e*Dd + j] = rtrW[gt];
    }
}

__global__ void k_prep_x(const float* __restrict__ x) {
    size_t i = (size_t)blockIdx.x * 256 + threadIdx.x;
    const float4* p = (const float4*)(x + i*8);
    float4 a = p[0], b = p[1];
    uint32_t q[4];
    q[0] = quant_f16(a.x, a.y); q[1] = quant_f16(a.z, a.w);
    q[2] = quant_f16(b.x, b.y); q[3] = quant_f16(b.z, b.w);
    *(uint4*)(g_xq + i*4) = *(uint4*)q;
}

// transpose + quantize: W[e][K][N] fp32 -> out[e][N][K/2] half2 (single plane)
template<int WHICH>  // 1: W1 512x2048, 2: W2 2048x512
__global__ __launch_bounds__(256) void k_prep_w(const float* __restrict__ W) {
    const int K = (WHICH == 2) ? Hh : Dd;
    const int N = (WHICH == 1) ? Hh : Dd;
    uint32_t* oq = (WHICH == 1) ? g_w1q : g_w2q;
    __shared__ float ts[64][65];
    int e = blockIdx.z;
    int n0 = blockIdx.x * 64, k0 = blockIdx.y * 64;
    const float* src = W + (size_t)e * K * N;
    int t = threadIdx.x;
    int lr = t >> 4, lc4 = (t & 15) * 4;
#pragma unroll
    for (int q = 0; q < 4; q++) {
        int kr = lr + q*16;
        float4 v = *(const float4*)(src + (size_t)(k0 + kr) * N + n0 + lc4);
        ts[kr][lc4] = v.x; ts[kr][lc4+1] = v.y; ts[kr][lc4+2] = v.z; ts[kr][lc4+3] = v.w;
    }
    __syncthreads();
    int hl = t >> 2, quarter = t & 3;
    uint32_t qw[8];
#pragma unroll
    for (int j = 0; j < 8; j++) {
        int d = quarter*16 + j*2;
        qw[j] = quant_f16(ts[d][hl], ts[d+1][hl]);
    }
    size_t ob = ((size_t)e * N + n0 + hl) * (K >> 1) + (k0 >> 1) + quarter*8;
    *(uint4*)(oq + ob)     = *(uint4*)&qw[0];
    *(uint4*)(oq + ob + 4) = *(uint4*)&qw[4];
}

__global__ void k_ln(const float* __restrict__ x, const float* __restrict__ ctx,
                     const float* __restrict__ quality,
                     const float* __restrict__ rn_g, const float* __restrict__ rn_b,
                     const float* __restrict__ cn_g, const float* __restrict__ cn_b,
                     const float* __restrict__ ctx_b,
                     const float* __restrict__ qual_W, const float* __restrict__ qual_b)
{
    if (blockIdx.x == 0 && threadIdx.x < Ee) g_ecount[threadIdx.x] = 0;
    int warp = threadIdx.x >> 5, lane = threadIdx.x & 31;
    int t = blockIdx.x * 8 + warp;
    const float2* xr = (const float2*)(x + (size_t)t * Dd);
    const float2* cr = (const float2*)(ctx + (size_t)t * Dd);
    float2 xv[8], cv[8];
    float xs = 0.f, xs2 = 0.f, cs = 0.f, cs2 = 0.f;
#pragma unroll
    for (int i = 0; i < 8; i++) {
        int w = i*32 + lane;
        float2 a = xr[w], c2 = cr[w];
        xv[i] = a; cv[i] = c2;
        xs += a.x + a.y; xs2 += a.x*a.x + a.y*a.y;
        cs += c2.x + c2.y; cs2 += c2.x*c2.x + c2.y*c2.y;
    }
#pragma unroll
    for (int o = 16; o > 0; o >>= 1) {
        xs  += __shfl_xor_sync(~0u, xs,  o);
        xs2 += __shfl_xor_sync(~0u, xs2, o);
        cs  += __shfl_xor_sync(~0u, cs,  o);
        cs2 += __shfl_xor_sync(~0u, cs2, o);
    }
    const float invD = 1.f / (float)Dd;
    float mx = xs * invD, vx = xs2 * invD - mx*mx;
    float mc = cs * invD, vc = cs2 * invD - mc*mc;
    float rx = rsqrtf(vx + 1e-5f);
    float rc = rsqrtf(vc + 1e-5f);
    float q = quality[t / Ss];
#pragma unroll
    for (int i = 0; i < 8; i++) {
        int w = i*32 + lane;
        int d = 2*w;
        float c0 = (cv[i].x - mc) * rc * cn_g[d]   + cn_b[d];
        float c1 = (cv[i].y - mc) * rc * cn_g[d+1] + cn_b[d+1];
        *(float2*)(g_lnc + (size_t)t*Dd + d) = make_float2(c0, c1);
        float b0 = (xv[i].x - mx) * rx * rn_g[d]   + rn_b[d]   + q*qual_W[d]   + qual_b[d]   + ctx_b[d];
        float b1 = (xv[i].y - mx) * rx * rn_g[d+1] + rn_b[d+1] + q*qual_W[d+1] + qual_b[d+1] + ctx_b[d+1];
        *(float2*)(g_base + (size_t)t*Dd + d) = make_float2(b0, b1);
    }
}

// ---------------- pipelined mma.sync GEMM (BKK=128/iter, 2-stage, fp16 1-MMA) ----------------
// MODE 1: h = gelu(x[tok]@W1+b1), fp16 output    MODE 2: out += gate*(h@W2+b2) (atomic)
template<int MODE>
__global__ __launch_bounds__(256, 1)
void k_gemm(const float* __restrict__ bias, float* __restrict__ out)
{
    extern __shared__ char smc[];
    __shared__ int sPair[128];
    uint32_t smem_u32 = smem_u32_of(smc);
    int tid = threadIdx.x, lane = tid & 31, wid = tid >> 5;
    int warpM = wid >> 1, warpN = wid & 1;
    int e = blockIdx.z;
    int n0 = blockIdx.x * 128, m0 = blockIdx.y * 128;

    int cnt = g_ecount[e];
    if (m0 >= cnt) return;
    if (tid < 128) {
        int gm = m0 + tid;
        sPair[tid] = g_elist[e*NTOK + (gm < cnt ? gm : 0)];
    }
    __syncthreads();

    // loader role: one row per thread-pair; 8 x 16B chunks each (half of 256B row-slab)
    int lrow = tid >> 1, lhalf = tid & 1;     // row 0..127, half 0/1 of 64-word span
    const uint32_t *Aq, *Bq;
    size_t aR0, bR0;
    int NT, KWw;
    if (MODE == 1) {
        Aq = g_xq; Bq = g_w1q + (size_t)e * Hh * (Dd/2);
        KWw = Dd/2; NT = Dd/128;
        aR0 = (size_t)(sPair[lrow] >> 1) * KWw;
        bR0 = (size_t)(n0 + lrow) * KWw;
    } else {
        Aq = g_hq; Bq = g_w2q + (size_t)e * Dd * (Hh/2);
        KWw = Hh/2; NT = Hh/128;
        aR0 = (size_t)sPair[lrow] * KWw;
        bR0 = (size_t)(n0 + lrow) * KWw;
    }
    uint32_t soff = ((uint32_t)lrow * PLW + lhalf*32) * 4;   // byte offset in plane
    uint32_t kq = (uint32_t)lhalf * 32;                       // word offset in k-span

#define ISSUE(sidx, it) do {                                                   \
        uint32_t db = smem_u32 + (uint32_t)(sidx)*STAGE_B;                     \
        size_t kw = (size_t)(it)*64 + kq;                                      \
        _Pragma("unroll")                                                      \
        for (int j = 0; j < 8; j++) {                                          \
            CPA(db + 0*PLANE_B + soff + j*16, (const void*)(Aq + aR0 + kw + j*4)); \
            CPA(db + 1*PLANE_B + soff + j*16, (const void*)(Bq + bR0 + kw + j*4)); \
        }                                                                      \
        CPA_COMMIT();                                                          \
    } while (0)

    float acc[2][8][4];
#pragma unroll
    for (int i = 0; i < 2; i++)
#pragma unroll
        for (int j = 0; j < 8; j++)
#pragma unroll
            for (int q = 0; q < 4; q++) acc[i][j][q] = 0.f;

    int lr = lane & 7, lt = lane >> 3;

    ISSUE(0, 0);
    ISSUE(1, 1);

    for (int it = 0; it < NT; it++) {
        int s = it & 1;
        CPA_WAIT1();                 // 2 pending -> oldest (stage s) complete
        __syncthreads();

        uint32_t base = smem_u32 + (uint32_t)s * STAGE_B;
#pragma unroll
        for (int ks = 0; ks < 8; ks++) {
            uint32_t ah[2][4];
#pragma unroll
            for (int am = 0; am < 2; am++) {
                int row = warpM*32 + am*16 + (lt & 1)*8 + lr;
                uint32_t off = ((uint32_t)row * PLW + ks*8 + (lt >> 1)*4) * 4;
                ldsm4(base + 0*PLANE_B + off, ah[am][0], ah[am][1], ah[am][2], ah[am][3]);
            }
#pragma unroll
            for (int p = 0; p < 4; p++) {
                int nrow = warpN*64 + p*16 + (lt >> 1)*8 + lr;
                uint32_t boff = ((uint32_t)nrow * PLW + ks*8 + (lt & 1)*4) * 4;
                uint32_t bq0, bq1, bq2, bq3;
                ldsm4(base + 1*PLANE_B + boff, bq0, bq1, bq2, bq3);
#pragma unroll
                for (int am = 0; am < 2; am++) {
                    mma_f16(acc[am][2*p],   ah[am][0],ah[am][1],ah[am][2],ah[am][3], bq0, bq1);
                    mma_f16(acc[am][2*p+1], ah[am][0],ah[am][1],ah[am][2],ah[am][3], bq2, bq3);
                }
            }
        }
        __syncthreads();             // all warps done reading stage s
        if (it + 2 < NT) ISSUE(s, it + 2);
        else CPA_COMMIT();           // tail: keep pending-group count constant
    }
#undef ISSUE

    // ---------------- epilogue ----------------
#pragma unroll
    for (int am = 0; am < 2; am++) {
#pragma unroll
        for (int bn = 0; bn < 8; bn++) {
            int col = n0 + warpN*64 + bn*8 + (lane & 3)*2;
            int mr0 = warpM*32 + am*16 + (lane >> 2);
#pragma unroll
            for (int half = 0; half < 2; half++) {
                int m = mr0 + half*8;
                if (m0 + m < cnt) {
                    int p = sPair[m];
                    if (MODE == 1) {
                        const float* br = bias + (size_t)e * Hh;
                        float v0 = acc[am][bn][half*2]   + br[col];
                        float v1 = acc[am][bn][half*2+1] + br[col+1];
                        v0 = 0.5f * v0 * (1.f + erff(v0 * 0.70710678118f));
                        v1 = 0.5f * v1 * (1.f + erff(v1 * 0.70710678118f));
                        g_hq[(size_t)p * (Hh/2) + (col >> 1)] = quant_f16(v0, v1);
                    } else {
                        float gate = g_gate[p];
                        int tok = p >> 1;
                        const float* br = bias + (size_t)e * Dd;
                        atomicAdd(&out[(size_t)tok * Dd + col],   gate * (acc[am][bn][half*2]   + br[col]));
                        atomicAdd(&out[(size_t)tok * Dd + col+1], gate * (acc[am][bn][half*2+1] + br[col+1]));
                    }
                }
            }
        }
    }
}

// ---------------- Router: logits = lnc@M + base@WT + b ----------------
__global__ void k_router(const float* __restrict__ rtrb, const float* __restrict__ temp)
{
    __shared__ float sprob[8][8];
    __shared__ float slse2[8];
    __shared__ float sent[8];
    int warp = threadIdx.x >> 5, lane = threadIdx.x & 31;
    int t = blockIdx.x * 8 + warp;
    float lg[8] = {};
#pragma unroll
    for (int i = 0; i < 8; i++) {
        int w = i*32 + lane;
        float2 ln = ((const float2*)(g_lnc  + (size_t)t*Dd))[w];
        float2 bb = ((const float2*)(g_base + (size_t)t*Dd))[w];
#pragma unroll
        for (int e = 0; e < 8; e++) {
            float2 m  = *(const float2*)(g_M  + e*Dd + 2*w);
            float2 ww = *(const float2*)(g_WT + e*Dd + 2*w);
            lg[e] += ln.x*m.x + ln.y*m.y + bb.x*ww.x + bb.y*ww.y;
        }
    }
#pragma unroll
    for (int o = 16; o > 0; o >>= 1)
#pragma unroll
        for (int e = 0; e < 8; e++)
            lg[e] += __shfl_xor_sync(~0u, lg[e], o);
    if (lane == 0) {
        float invT = 1.f / fmaxf(temp[0], 0.25f);
        float l[8];
#pragma unroll
        for (int e = 0; e < 8; e++) l[e] = (lg[e] + rtrb[e]) * invT;
        float mx = l[0];
#pragma unroll
        for (int e = 1; e < 8; e++) mx = fmaxf(mx, l[e]);
        float ex[8], se = 0.f;
#pragma unroll
        for (int e = 0; e < 8; e++) { ex[e] = expf(l[e] - mx); se += ex[e]; }
        float lse = logf(se) + mx;
        float inv_se = 1.f / se;
        float ent = 0.f;
#pragma unroll
        for (int e = 0; e < 8; e++) {
            float p = ex[e] * inv_se;
            ent -= p * logf(fmaxf(p, 1e-9f));
            sprob[warp][e] = p;
        }
        slse2[warp] = lse * lse;
        sent[warp] = ent;
        int i0 = 0;
#pragma unroll
        for (int e = 1; e < 8; e++) if (l[e] > l[i0]) i0 = e;
        int i1 = (i0 == 0) ? 1 : 0;
#pragma unroll
        for (int e = 0; e < 8; e++) { if (e == i0 || e == i1) continue; if (l[e] > l[i1]) i1 = e; }
        float d1 = expf(l[i1] - l[i0]);
        float g0 = 1.f / (1.f + d1);
        float g1 = d1 * g0;
        int p0 = t*2, p1 = t*2 + 1;
        g_gate[p0] = g0; g_gate[p1] = g1;
        int s0 = atomicAdd(&g_ecount[i0], 1);
        g_elist[i0*NTOK + s0] = p0;
        int s1 = atomicAdd(&g_ecount[i1], 1);
        g_elist[i1*NTOK + s1] = p1;
    }
    __syncthreads();
    int tid = threadIdx.x;
    if (tid < 8) {
        float s = 0.f;
#pragma unroll
        for (int w = 0; w < 8; w++) s += sprob[w][tid];
        g_part[blockIdx.x*10 + tid] = s;
    } else if (tid == 8) {
        float s = 0.f;
#pragma unroll
        for (int w = 0; w < 8; w++) s += slse2[w];
        g_part[blockIdx.x*10 + 8] = s;
    } else if (tid == 9) {
        float s = 0.f;
#pragma unroll
        for (int w = 0; w < 8; w++) s += sent[w];
        g_part[blockIdx.x*10 + 9] = s;
    }
}

// ---------------- finalize ----------------
__global__ void k_finalize(float* __restrict__ out)
{
    __shared__ float ssum[10];
    int tid = threadIdx.x;
    if (tid < 10) {
        float s = 0.f;
        for (int b = 0; b < NRB; b++) s += g_part[b*10 + tid];
        ssum[tid] = s;
    }
    __syncthreads();
    if (tid == 0) {
        const float inv = 1.f / (float)NTOK;
        float lb = 0.f;
#pragma unroll
        for (int e = 0; e < Ee; e++) {
            float d = ssum[e] * inv - 1.f / (float)Ee;
            lb += d * d;
        }
        lb *= 1.f / (float)Ee;
        float rz = ssum[8] * inv;
        float ent = ssum[9] * inv;
        out[NTOK*Dd + 0] = lb;
        out[NTOK*Dd + 1] = rz;
        out[NTOK*Dd + 2] = ent;
        out[NTOK*Dd + 3] = lb + 0.001f * rz - 0.001f * ent;
    }
}

// ---------------- launch ----------------
extern "C" void kernel_launch(void* const* d_in, const int* in_sizes, int n_in,
                              void* d_out, int out_size)
{
    const float* x       = (const float*)d_in[0];
    const float* ctx     = (const float*)d_in[1];
    const float* quality = (const float*)d_in[2];
    const float* rn_g    = (const float*)d_in[3];
    const float* rn_b    = (const float*)d_in[4];
    const float* cn_g    = (const float*)d_in[5];
    const float* cn_b    = (const float*)d_in[6];
    const float* ctx_W   = (const float*)d_in[7];
    const float* ctx_b   = (const float*)d_in[8];
    const float* qual_W  = (const float*)d_in[9];
    const float* qual_b  = (const float*)d_in[10];
    const float* rtr_W   = (const float*)d_in[11];
    const float* rtr_b   = (const float*)d_in[12];
    const float* temp    = (const float*)d_in[13];
    const float* W1      = (const float*)d_in[14];
    const float* b1      = (const float*)d_in[15];
    const float* W2      = (const float*)d_in[16];
    const float* b2      = (const float*)d_in[17];
    float* out = (float*)d_out;

    static bool s_init = false;
    static cudaStream_t s1, s2;
    static cudaEvent_t evRoot, evM, evX, evZ, evP1, evP2, evR, evF;
    if (!s_init) {
        cudaFuncSetAttribute(k_gemm<1>, cudaFuncAttributeMaxDynamicSharedMemorySize, TC_SMEM);
        cudaFuncSetAttribute(k_gemm<2>, cudaFuncAttributeMaxDynamicSharedMemorySize, TC_SMEM);
        cudaStreamCreateWithFlags(&s1, cudaStreamNonBlocking);
        cudaStreamCreateWithFlags(&s2, cudaStreamNonBlocking);
        cudaEventCreateWithFlags(&evRoot, cudaEventDisableTiming);
        cudaEventCreateWithFlags(&evM,   cudaEventDisableTiming);
        cudaEventCreateWithFlags(&evX,   cudaEventDisableTiming);
        cudaEventCreateWithFlags(&evZ,   cudaEventDisableTiming);
        cudaEventCreateWithFlags(&evP1,  cudaEventDisableTiming);
        cudaEventCreateWithFlags(&evP2,  cudaEventDisableTiming);
        cudaEventCreateWithFlags(&evR,   cudaEventDisableTiming);
        cudaEventCreateWithFlags(&evF,   cudaEventDisableTiming);
        s_init = true;
    }

    // fork both side streams off main (graph-capture-safe event pattern)
    cudaEventRecord(evRoot, 0);
    cudaStreamWaitEvent(s1, evRoot, 0);
    cudaStreamWaitEvent(s2, evRoot, 0);

    // s1: weight packing (gemm1's W first — it gates the critical path)
    k_prep_w<1><<<dim3(Hh/64, Dd/64, Ee), 256, 0, s1>>>(W1);
    cudaEventRecord(evP1, s1);
    k_prep_w<2><<<dim3(Dd/64, Hh/64, Ee), 256, 0, s1>>>(W2);
    cudaEventRecord(evP2, s1);

    // s2: router fold matrices first (gates router), then zero-fill, x quantize
    k_prep_M<<<Dd/8, 256, 0, s2>>>(ctx_W, rtr_W);
    cudaEventRecord(evM, s2);
    k_zero_out<<<(NTOK*Dd)/(4*256), 256, 0, s2>>>(out);
    cudaEventRecord(evZ, s2);
    k_prep_x<<<(NTOK*Dd)/(8*256), 256, 0, s2>>>(x);
    cudaEventRecord(evX, s2);

    // main: ln -> router -> gemm1 -> gemm2; finalize on s2 after router (joined before gemm2)
    k_ln<<<NTOK/8, 256>>>(x, ctx, quality, rn_g, rn_b, cn_g, cn_b, ctx_b, qual_W, qual_b);
    cudaStreamWaitEvent(0, evM, 0);
    k_router<<<NTOK/8, 256>>>(rtr_b, temp);
    cudaEventRecord(evR, 0);
    cudaStreamWaitEvent(s2, evR, 0);
    k_finalize<<<1, 32, 0, s2>>>(out);
    cudaEventRecord(evF, s2);
    cudaStreamWaitEvent(0, evX, 0);
    cudaStreamWaitEvent(0, evP1, 0);
    k_gemm<1><<<dim3(Hh/128, NTOK/128, Ee), 256, TC_SMEM>>>(b1, nullptr);
    cudaStreamWaitEvent(0, evP2, 0);
    cudaStreamWaitEvent(0, evZ, 0);
    cudaStreamWaitEvent(0, evF, 0);
    k_gemm<2><<<dim3(Dd/128, NTOK/128, Ee), 256, TC_SMEM>>>(b2, out);
}

// round 17
// speedup vs baseline: 1.1271x; 1.1271x over previous
#include <cuda_runtime.h>
#include <cuda_fp16.h>
#include <math.h>
#include <stdint.h>

#define Bb   4
#define Ss   512
#define Dd   512
#define Hh   2048
#define Ee   8
#define NTOK (Bb*Ss)
#define NPAIR (NTOK*2)
#define NRB  (NTOK/8)                   // router blocks = 256

#define PLW     36                      // smem row pitch in words (32 used + 4 pad)
#define PLANE_W (128*PLW)               // 4608 words
#define PLANE_B (PLANE_W*4)             // 18432 B
#define STAGE_B (2*PLANE_B)             // Aq, Bq = 36864 B
#define NSTAGE  4
#define TC_SMEM (NSTAGE*STAGE_B)        // 147456 B (1 CTA/SM)

// ---------------- device scratch ----------------
__device__ float    g_base[NTOK*Dd];
__device__ float    g_lnc[NTOK*Dd];     // LN(context) fp32 (router only)
__device__ uint32_t g_xq[NTOK*(Dd/2)];  // x fp16 quantized
__device__ uint32_t g_w1q[Ee*Hh*(Dd/2)];  // W1^T fp16 quantized
__device__ uint32_t g_w2q[Ee*Dd*(Hh/2)];  // W2^T fp16 quantized
__device__ uint32_t g_hq[NPAIR*(Hh/2)];   // h fp16 quantized
__device__ float    g_M[Ee*Dd];         // (ctxW @ rtrW)^T : [e][d]
__device__ float    g_WT[Ee*Dd];        // rtrW^T : [e][d]
__device__ int      g_elist[Ee*NTOK];
__device__ int      g_ecount[Ee];
__device__ float    g_gate[NPAIR];
__device__ float    g_part[NRB*10];     // per-router-block partials

// ---------------- helpers ----------------
__device__ __forceinline__ uint32_t smem_u32_of(const void* p) {
    uint32_t a;
    asm("{ .reg .u64 t; cvta.to.shared.u64 t, %1; cvt.u32.u64 %0, t; }" : "=r"(a) : "l"(p));
    return a;
}
__device__ __forceinline__ uint32_t quant_f16(float x0, float x1) {
    __half2 h = __floats2half2_rn(x0, x1);
    return *reinterpret_cast<uint32_t*>(&h);
}
__device__ __forceinline__ void mma_f16(float c[4],
        uint32_t a0, uint32_t a1, uint32_t a2, uint32_t a3, uint32_t b0, uint32_t b1) {
    asm volatile(
        "mma.sync.aligned.m16n8k16.row.col.f32.f16.f16.f32 "
        "{%0,%1,%2,%3}, {%4,%5,%6,%7}, {%8,%9}, {%0,%1,%2,%3};"
        : "+f"(c[0]), "+f"(c[1]), "+f"(c[2]), "+f"(c[3])
        : "r"(a0), "r"(a1), "r"(a2), "r"(a3), "r"(b0), "r"(b1));
}
__device__ __forceinline__ void ldsm4(uint32_t a, uint32_t& r0, uint32_t& r1,
                                      uint32_t& r2, uint32_t& r3) {
    asm volatile("ldmatrix.sync.aligned.m8n8.x4.shared.b16 {%0,%1,%2,%3}, [%4];"
        : "=r"(r0), "=r"(r1), "=r"(r2), "=r"(r3) : "r"(a));
}
#define CPA(dst, src) asm volatile("cp.async.cg.shared.global [%0], [%1], 16;" :: "r"(dst), "l"(src))
#define CPA_COMMIT()  asm volatile("cp.async.commit_group;" ::: "memory")
#define CPA_WAIT2()   asm volatile("cp.async.wait_group 2;" ::: "memory")

// ---------------- prep kernels ----------------
__global__ void k_zero_out(float* __restrict__ out) {
    ((float4*)out)[(size_t)blockIdx.x * 256 + threadIdx.x] = make_float4(0.f, 0.f, 0.f, 0.f);
}

// M^T[e][i] = sum_j ctxW[i][j] * rtrW[j][e]; also rtrW^T
__global__ void k_prep_M(const float* __restrict__ ctxW, const float* __restrict__ rtrW) {
    int warp = threadIdx.x >> 5, lane = threadIdx.x & 31;
    int i = blockIdx.x * 8 + warp;
    float acc[8] = {};
#pragma unroll
    for (int jj = 0; jj < 16; jj++) {
        int j = jj*32 + lane;
        float v = ctxW[(size_t)i * Dd + j];
        const float4* w = (const float4*)(rtrW + (size_t)j * Ee);
        float4 w0 = w[0], w1 = w[1];
        acc[0] += v*w0.x; acc[1] += v*w0.y; acc[2] += v*w0.z; acc[3] += v*w0.w;
        acc[4] += v*w1.x; acc[5] += v*w1.y; acc[6] += v*w1.z; acc[7] += v*w1.w;
    }
#pragma unroll
    for (int o = 16; o > 0; o >>= 1)
#pragma unroll
        for (int e = 0; e < 8; e++)
            acc[e] += __shfl_xor_sync(~0u, acc[e], o);
    if (lane < 8) g_M[lane*Dd + i] = acc[lane];
    int gt = blockIdx.x * 256 + threadIdx.x;
    if (gt < Dd*Ee) {
        int j = gt >> 3, e = gt & 7;
        g_WT[e*Dd + j] = rtrW[gt];
    }
}

__global__ void k_prep_x(const float* __restrict__ x) {
    size_t i = (size_t)blockIdx.x * 256 + threadIdx.x;
    const float4* p = (const float4*)(x + i*8);
    float4 a = p[0], b = p[1];
    uint32_t q[4];
    q[0] = quant_f16(a.x, a.y); q[1] = quant_f16(a.z, a.w);
    q[2] = quant_f16(b.x, b.y); q[3] = quant_f16(b.z, b.w);
    *(uint4*)(g_xq + i*4) = *(uint4*)q;
}

// transpose + quantize: W[e][K][N] fp32 -> out[e][N][K/2] half2 (single plane)
template<int WHICH>  // 1: W1 512x2048, 2: W2 2048x512
__global__ __launch_bounds__(256) void k_prep_w(const float* __restrict__ W) {
    const int K = (WHICH == 2) ? Hh : Dd;
    const int N = (WHICH == 1) ? Hh : Dd;
    uint32_t* oq = (WHICH == 1) ? g_w1q : g_w2q;
    __shared__ float ts[64][65];
    int e = blockIdx.z;
    int n0 = blockIdx.x * 64, k0 = blockIdx.y * 64;
    const float* src = W + (size_t)e * K * N;
    int t = threadIdx.x;
    int lr = t >> 4, lc4 = (t & 15) * 4;
#pragma unroll
    for (int q = 0; q < 4; q++) {
        int kr = lr + q*16;
        float4 v = *(const float4*)(src + (size_t)(k0 + kr) * N + n0 + lc4);
        ts[kr][lc4] = v.x; ts[kr][lc4+1] = v.y; ts[kr][lc4+2] = v.z; ts[kr][lc4+3] = v.w;
    }
    __syncthreads();
    int hl = t >> 2, quarter = t & 3;
    uint32_t qw[8];
#pragma unroll
    for (int j = 0; j < 8; j++) {
        int d = quarter*16 + j*2;
        qw[j] = quant_f16(ts[d][hl], ts[d+1][hl]);
    }
    size_t ob = ((size_t)e * N + n0 + hl) * (K >> 1) + (k0 >> 1) + quarter*8;
    *(uint4*)(oq + ob)     = *(uint4*)&qw[0];
    *(uint4*)(oq + ob + 4) = *(uint4*)&qw[4];
}

__global__ void k_ln(const float* __restrict__ x, const float* __restrict__ ctx,
                     const float* __restrict__ quality,
                     const float* __restrict__ rn_g, const float* __restrict__ rn_b,
                     const float* __restrict__ cn_g, const float* __restrict__ cn_b,
                     const float* __restrict__ ctx_b,
                     const float* __restrict__ qual_W, const float* __restrict__ qual_b)
{
    if (blockIdx.x == 0 && threadIdx.x < Ee) g_ecount[threadIdx.x] = 0;
    int warp = threadIdx.x >> 5, lane = threadIdx.x & 31;
    int t = blockIdx.x * 8 + warp;
    const float2* xr = (const float2*)(x + (size_t)t * Dd);
    const float2* cr = (const float2*)(ctx + (size_t)t * Dd);
    float2 xv[8], cv[8];
    float xs = 0.f, xs2 = 0.f, cs = 0.f, cs2 = 0.f;
#pragma unroll
    for (int i = 0; i < 8; i++) {
        int w = i*32 + lane;
        float2 a = xr[w], c2 = cr[w];
        xv[i] = a; cv[i] = c2;
        xs += a.x + a.y; xs2 += a.x*a.x + a.y*a.y;
        cs += c2.x + c2.y; cs2 += c2.x*c2.x + c2.y*c2.y;
    }
#pragma unroll
    for (int o = 16; o > 0; o >>= 1) {
        xs  += __shfl_xor_sync(~0u, xs,  o);
        xs2 += __shfl_xor_sync(~0u, xs2, o);
        cs  += __shfl_xor_sync(~0u, cs,  o);
        cs2 += __shfl_xor_sync(~0u, cs2, o);
    }
    const float invD = 1.f / (float)Dd;
    float mx = xs * invD, vx = xs2 * invD - mx*mx;
    float mc = cs * invD, vc = cs2 * invD - mc*mc;
    float rx = rsqrtf(vx + 1e-5f);
    float rc = rsqrtf(vc + 1e-5f);
    float q = quality[t / Ss];
#pragma unroll
    for (int i = 0; i < 8; i++) {
        int w = i*32 + lane;
        int d = 2*w;
        float c0 = (cv[i].x - mc) * rc * cn_g[d]   + cn_b[d];
        float c1 = (cv[i].y - mc) * rc * cn_g[d+1] + cn_b[d+1];
        *(float2*)(g_lnc + (size_t)t*Dd + d) = make_float2(c0, c1);
        float b0 = (xv[i].x - mx) * rx * rn_g[d]   + rn_b[d]   + q*qual_W[d]   + qual_b[d]   + ctx_b[d];
        float b1 = (xv[i].y - mx) * rx * rn_g[d+1] + rn_b[d+1] + q*qual_W[d+1] + qual_b[d+1] + ctx_b[d+1];
        *(float2*)(g_base + (size_t)t*Dd + d) = make_float2(b0, b1);
    }
}

// ---------------- pipelined mma.sync GEMM (BKK=64, 4-stage, fp16 1-MMA) ----------------
// MODE 1: h = gelu(x[tok]@W1+b1), fp16 output    MODE 2: out += gate*(h@W2+b2) (atomic)
template<int MODE>
__global__ __launch_bounds__(256, 1)
void k_gemm(const float* __restrict__ bias, float* __restrict__ out)
{
    extern __shared__ char smc[];
    __shared__ int sPair[128];
    uint32_t smem_u32 = smem_u32_of(smc);
    int tid = threadIdx.x, lane = tid & 31, wid = tid >> 5;
    int warpM = wid >> 1, warpN = wid & 1;
    int e = blockIdx.z;
    int n0 = blockIdx.x * 128, m0 = blockIdx.y * 128;

    int cnt = g_ecount[e];
    if (m0 >= cnt) return;
    if (tid < 128) {
        int gm = m0 + tid;
        sPair[tid] = g_elist[e*NTOK + (gm < cnt ? gm : 0)];
    }
    __syncthreads();

    // loader role: one row per thread-pair; 4 x 16B chunks each (64 B of the 128B row-iter)
    int lrow = tid >> 1, lhalf = tid & 1;     // row 0..127, half 0/1 of 32-word span
    const uint32_t *Aq, *Bq;
    size_t aR0, bR0;
    int NT, KWw;
    if (MODE == 1) {
        Aq = g_xq; Bq = g_w1q + (size_t)e * Hh * (Dd/2);
        KWw = Dd/2; NT = Dd/64;
        aR0 = (size_t)(sPair[lrow] >> 1) * KWw;
        bR0 = (size_t)(n0 + lrow) * KWw;
    } else {
        Aq = g_hq; Bq = g_w2q + (size_t)e * Dd * (Hh/2);
        KWw = Hh/2; NT = Hh/64;
        aR0 = (size_t)sPair[lrow] * KWw;
        bR0 = (size_t)(n0 + lrow) * KWw;
    }
    uint32_t soff = ((uint32_t)lrow * PLW + lhalf*16) * 4;   // byte offset in plane
    uint32_t kq = (uint32_t)lhalf * 16;                       // word offset in k-span

#define ISSUE(sidx, it) do {                                                   \
        uint32_t db = smem_u32 + (uint32_t)(sidx)*STAGE_B;                     \
        size_t kw = (size_t)(it)*32 + kq;                                      \
        _Pragma("unroll")                                                      \
        for (int j = 0; j < 4; j++) {                                          \
            CPA(db + 0*PLANE_B + soff + j*16, (const void*)(Aq + aR0 + kw + j*4)); \
            CPA(db + 1*PLANE_B + soff + j*16, (const void*)(Bq + bR0 + kw + j*4)); \
        }                                                                      \
        CPA_COMMIT();                                                          \
    } while (0)

    float acc[2][8][4];
#pragma unroll
    for (int i = 0; i < 2; i++)
#pragma unroll
        for (int j = 0; j < 8; j++)
#pragma unroll
            for (int q = 0; q < 4; q++) acc[i][j][q] = 0.f;

    int lr = lane & 7, lt = lane >> 3;

    ISSUE(0, 0);
    ISSUE(1, 1);
    ISSUE(2, 2);

    for (int it = 0; it < NT; it++) {
        int s = it & 3;
        CPA_WAIT2();                 // 3 pending -> oldest (stage s) complete
        __syncthreads();
        if (it + 3 < NT) ISSUE((it + 3) & 3, it + 3);
        else CPA_COMMIT();           // tail: keep pending-group count constant

        uint32_t base = smem_u32 + (uint32_t)s * STAGE_B;
#pragma unroll
        for (int ks = 0; ks < 4; ks++) {
            uint32_t ah[2][4];
#pragma unroll
            for (int am = 0; am < 2; am++) {
                int row = warpM*32 + am*16 + (lt & 1)*8 + lr;
                uint32_t off = ((uint32_t)row * PLW + ks*8 + (lt >> 1)*4) * 4;
                ldsm4(base + 0*PLANE_B + off, ah[am][0], ah[am][1], ah[am][2], ah[am][3]);
            }
#pragma unroll
            for (int p = 0; p < 4; p++) {
                int nrow = warpN*64 + p*16 + (lt >> 1)*8 + lr;
                uint32_t boff = ((uint32_t)nrow * PLW + ks*8 + (lt & 1)*4) * 4;
                uint32_t bq0, bq1, bq2, bq3;
                ldsm4(base + 1*PLANE_B + boff, bq0, bq1, bq2, bq3);
#pragma unroll
                for (int am = 0; am < 2; am++) {
                    mma_f16(acc[am][2*p],   ah[am][0],ah[am][1],ah[am][2],ah[am][3], bq0, bq1);
                    mma_f16(acc[am][2*p+1], ah[am][0],ah[am][1],ah[am][2],ah[am][3], bq2, bq3);
                }
            }
        }
    }
#undef ISSUE

    // ---------------- epilogue ----------------
#pragma unroll
    for (int am = 0; am < 2; am++) {
#pragma unroll
        for (int bn = 0; bn < 8; bn++) {
            int col = n0 + warpN*64 + bn*8 + (lane & 3)*2;
            int mr0 = warpM*32 + am*16 + (lane >> 2);
#pragma unroll
            for (int half = 0; half < 2; half++) {
                int m = mr0 + half*8;
                if (m0 + m < cnt) {
                    int p = sPair[m];
                    if (MODE == 1) {
                        const float* br = bias + (size_t)e * Hh;
                        float v0 = acc[am][bn][half*2]   + br[col];
                        float v1 = acc[am][bn][half*2+1] + br[col+1];
                        v0 = 0.5f * v0 * (1.f + erff(v0 * 0.70710678118f));
                        v1 = 0.5f * v1 * (1.f + erff(v1 * 0.70710678118f));
                        g_hq[(size_t)p * (Hh/2) + (col >> 1)] = quant_f16(v0, v1);
                    } else {
                        float gate = g_gate[p];
                        int tok = p >> 1;
                        const float* br = bias + (size_t)e * Dd;
                        atomicAdd(&out[(size_t)tok * Dd + col],   gate * (acc[am][bn][half*2]   + br[col]));
                        atomicAdd(&out[(size_t)tok * Dd + col+1], gate * (acc[am][bn][half*2+1] + br[col+1]));
                    }
                }
            }
        }
    }
}

// ---------------- Router: logits = lnc@M + base@WT + b ----------------
__global__ void k_router(const float* __restrict__ rtrb, const float* __restrict__ temp)
{
    __shared__ float sprob[8][8];
    __shared__ float slse2[8];
    __shared__ float sent[8];
    int warp = threadIdx.x >> 5, lane = threadIdx.x & 31;
    int t = blockIdx.x * 8 + warp;
    float lg[8] = {};
#pragma unroll
    for (int i = 0; i < 8; i++) {
        int w = i*32 + lane;
        float2 ln = ((const float2*)(g_lnc  + (size_t)t*Dd))[w];
        float2 bb = ((const float2*)(g_base + (size_t)t*Dd))[w];
#pragma unroll
        for (int e = 0; e < 8; e++) {
            float2 m  = *(const float2*)(g_M  + e*Dd + 2*w);
            float2 ww = *(const float2*)(g_WT + e*Dd + 2*w);
            lg[e] += ln.x*m.x + ln.y*m.y + bb.x*ww.x + bb.y*ww.y;
        }
    }
#pragma unroll
    for (int o = 16; o > 0; o >>= 1)
#pragma unroll
        for (int e = 0; e < 8; e++)
            lg[e] += __shfl_xor_sync(~0u, lg[e], o);
    if (lane == 0) {
        float invT = 1.f / fmaxf(temp[0], 0.25f);
        float l[8];
#pragma unroll
        for (int e = 0; e < 8; e++) l[e] = (lg[e] + rtrb[e]) * invT;
        float mx = l[0];
#pragma unroll
        for (int e = 1; e < 8; e++) mx = fmaxf(mx, l[e]);
        float ex[8], se = 0.f;
#pragma unroll
        for (int e = 0; e < 8; e++) { ex[e] = expf(l[e] - mx); se += ex[e]; }
        float lse = logf(se) + mx;
        float inv_se = 1.f / se;
        float ent = 0.f;
#pragma unroll
        for (int e = 0; e < 8; e++) {
            float p = ex[e] * inv_se;
            ent -= p * logf(fmaxf(p, 1e-9f));
            sprob[warp][e] = p;
        }
        slse2[warp] = lse * lse;
        sent[warp] = ent;
        int i0 = 0;
#pragma unroll
        for (int e = 1; e < 8; e++) if (l[e] > l[i0]) i0 = e;
        int i1 = (i0 == 0) ? 1 : 0;
#pragma unroll
        for (int e = 0; e < 8; e++) { if (e == i0 || e == i1) continue; if (l[e] > l[i1]) i1 = e; }
        float d1 = expf(l[i1] - l[i0]);
        float g0 = 1.f / (1.f + d1);
        float g1 = d1 * g0;
        int p0 = t*2, p1 = t*2 + 1;
        g_gate[p0] = g0; g_gate[p1] = g1;
        int s0 = atomicAdd(&g_ecount[i0], 1);
        g_elist[i0*NTOK + s0] = p0;
        int s1 = atomicAdd(&g_ecount[i1], 1);
        g_elist[i1*NTOK + s1] = p1;
    }
    __syncthreads();
    int tid = threadIdx.x;
    if (tid < 8) {
        float s = 0.f;
#pragma unroll
        for (int w = 0; w < 8; w++) s += sprob[w][tid];
        g_part[blockIdx.x*10 + tid] = s;
    } else if (tid == 8) {
        float s = 0.f;
#pragma unroll
        for (int w = 0; w < 8; w++) s += slse2[w];
        g_part[blockIdx.x*10 + 8] = s;
    } else if (tid == 9) {
        float s = 0.f;
#pragma unroll
        for (int w = 0; w < 8; w++) s += sent[w];
        g_part[blockIdx.x*10 + 9] = s;
    }
}

// ---------------- finalize ----------------
__global__ void k_finalize(float* __restrict__ out)
{
    __shared__ float ssum[10];
    int tid = threadIdx.x;
    if (tid < 10) {
        float s = 0.f;
        for (int b = 0; b < NRB; b++) s += g_part[b*10 + tid];
        ssum[tid] = s;
    }
    __syncthreads();
    if (tid == 0) {
        const float inv = 1.f / (float)NTOK;
        float lb = 0.f;
#pragma unroll
        for (int e = 0; e < Ee; e++) {
            float d = ssum[e] * inv - 1.f / (float)Ee;
            lb += d * d;
        }
        lb *= 1.f / (float)Ee;
        float rz = ssum[8] * inv;
        float ent = ssum[9] * inv;
        out[NTOK*Dd + 0] = lb;
        out[NTOK*Dd + 1] = rz;
        out[NTOK*Dd + 2] = ent;
        out[NTOK*Dd + 3] = lb + 0.001f * rz - 0.001f * ent;
    }
}

// ---------------- launch ----------------
extern "C" void kernel_launch(void* const* d_in, const int* in_sizes, int n_in,
                              void* d_out, int out_size)
{
    const float* x       = (const float*)d_in[0];
    const float* ctx     = (const float*)d_in[1];
    const float* quality = (const float*)d_in[2];
    const float* rn_g    = (const float*)d_in[3];
    const float* rn_b    = (const float*)d_in[4];
    const float* cn_g    = (const float*)d_in[5];
    const float* cn_b    = (const float*)d_in[6];
    const float* ctx_W   = (const float*)d_in[7];
    const float* ctx_b   = (const float*)d_in[8];
    const float* qual_W  = (const float*)d_in[9];
    const float* qual_b  = (const float*)d_in[10];
    const float* rtr_W   = (const float*)d_in[11];
    const float* rtr_b   = (const float*)d_in[12];
    const float* temp    = (const float*)d_in[13];
    const float* W1      = (const float*)d_in[14];
    const float* b1      = (const float*)d_in[15];
    const float* W2      = (const float*)d_in[16];
    const float* b2      = (const float*)d_in[17];
    float* out = (float*)d_out;

    static bool s_init = false;
    static cudaStream_t s1, s2;
    static cudaEvent_t evRoot, evM, evX, evZ, evP1, evP2, evR, evF;
    if (!s_init) {
        cudaFuncSetAttribute(k_gemm<1>, cudaFuncAttributeMaxDynamicSharedMemorySize, TC_SMEM);
        cudaFuncSetAttribute(k_gemm<2>, cudaFuncAttributeMaxDynamicSharedMemorySize, TC_SMEM);
        cudaStreamCreateWithFlags(&s1, cudaStreamNonBlocking);
        cudaStreamCreateWithFlags(&s2, cudaStreamNonBlocking);
        cudaEventCreateWithFlags(&evRoot, cudaEventDisableTiming);
        cudaEventCreateWithFlags(&evM,   cudaEventDisableTiming);
        cudaEventCreateWithFlags(&evX,   cudaEventDisableTiming);
        cudaEventCreateWithFlags(&evZ,   cudaEventDisableTiming);
        cudaEventCreateWithFlags(&evP1,  cudaEventDisableTiming);
        cudaEventCreateWithFlags(&evP2,  cudaEventDisableTiming);
        cudaEventCreateWithFlags(&evR,   cudaEventDisableTiming);
        cudaEventCreateWithFlags(&evF,   cudaEventDisableTiming);
        s_init = true;
    }

    // fork both side streams off main (graph-capture-safe event pattern)
    cudaEventRecord(evRoot, 0);
    cudaStreamWaitEvent(s1, evRoot, 0);
    cudaStreamWaitEvent(s2, evRoot, 0);

    // s1: weight packing (gemm1's W first — it gates the critical path)
    k_prep_w<1><<<dim3(Hh/64, Dd/64, Ee), 256, 0, s1>>>(W1);
    cudaEventRecord(evP1, s1);
    k_prep_w<2><<<dim3(Dd/64, Hh/64, Ee), 256, 0, s1>>>(W2);
    cudaEventRecord(evP2, s1);

    // s2: router fold matrices first (gates router), then zero-fill, x quantize
    k_prep_M<<<Dd/8, 256, 0, s2>>>(ctx_W, rtr_W);
    cudaEventRecord(evM, s2);
    k_zero_out<<<(NTOK*Dd)/(4*256), 256, 0, s2>>>(out);
    cudaEventRecord(evZ, s2);
    k_prep_x<<<(NTOK*Dd)/(8*256), 256, 0, s2>>>(x);
    cudaEventRecord(evX, s2);

    // main: ln -> router -> gemm1 -> gemm2; finalize on s2 after router (joined before gemm2)
    k_ln<<<NTOK/8, 256>>>(x, ctx, quality, rn_g, rn_b, cn_g, cn_b, ctx_b, qual_W, qual_b);
    cudaStreamWaitEvent(0, evM, 0);
    k_router<<<NTOK/8, 256>>>(rtr_b, temp);
    cudaEventRecord(evR, 0);
    cudaStreamWaitEvent(s2, evR, 0);
    k_finalize<<<1, 32, 0, s2>>>(out);
    cudaEventRecord(evF, s2);
    cudaStreamWaitEvent(0, evX, 0);
    cudaStreamWaitEvent(0, evP1, 0);
    k_gemm<1><<<dim3(Hh/128, NTOK/128, Ee), 256, TC_SMEM>>>(b1, nullptr);
    cudaStreamWaitEvent(0, evP2, 0);
    cudaStreamWaitEvent(0, evZ, 0);
    cudaStreamWaitEvent(0, evF, 0);
    k_gemm<2><<<dim3(Dd/128, NTOK/128, Ee), 256, TC_SMEM>>>(b2, out);
}